// round 11
// baseline (speedup 1.0000x reference)
#include <cuda_runtime.h>
#include <math.h>

typedef unsigned long long ULL;

// ---------------- f32x2 packed-math helpers (sm_100+) --------------------
__device__ __forceinline__ ULL bcast2(float v) {
    ULL r; asm("mov.b64 %0, {%1, %1};" : "=l"(r) : "f"(v)); return r;
}
__device__ __forceinline__ void fma2(ULL& d, ULL a, ULL b) {
    asm("fma.rn.f32x2 %0, %1, %2, %0;" : "+l"(d) : "l"(a), "l"(b));
}
__device__ __forceinline__ float2 unpack2(ULL v) {
    float2 f; asm("mov.b64 {%0, %1}, %2;" : "=f"(f.x), "=f"(f.y) : "l"(v)); return f;
}
__device__ __forceinline__ float ex2(float x) {
    float r; asm("ex2.approx.f32 %0, %1;" : "=f"(r) : "f"(x)); return r;
}

// ---------------- scratch buffers (no allocation allowed) ----------------
__device__ float g_Q[4096 * 256];
__device__ float g_K[4096 * 256];
__device__ float g_V[4096 * 256];
__device__ float g_O[4096 * 256];
__device__ float g_Msg[4096 * 256];
__device__ float g_H[4096 * 512];

// ---------------- GEMM core (f32x2) — R7/R10 proven version ---------------
template <bool RELU>
__device__ __forceinline__ void gemm_body(
    const float* __restrict__ A0, const float* __restrict__ A1, int kSplit,
    const float* __restrict__ W, const float* __restrict__ pe, bool rotary,
    float* __restrict__ C, int N, int K,
    float (*As)[16], float (*Ws)[64])
{
    const int tid = threadIdx.x;
    const int tx = tid & 15;
    const int ty = tid >> 4;
    const int m0 = blockIdx.y * 128;
    const int n0 = blockIdx.x * 64;

    const int ar = tid >> 2;
    const int ak = (tid & 3) * 4;
    const int wk = tid >> 4;
    const int wc = (tid & 15) * 4;

    ULL acc2[8][2];
#pragma unroll
    for (int i = 0; i < 8; i++) { acc2[i][0] = 0ull; acc2[i][1] = 0ull; }

    const int nk = K >> 4;
    float4 pa0, pa1, pw;

    pa0 = *(const float4*)(A0 + (size_t)(m0 + ar) * kSplit + ak);
    pa1 = *(const float4*)(A0 + (size_t)(m0 + ar + 64) * kSplit + ak);
    pw  = *(const float4*)(W + (size_t)wk * N + n0 + wc);
    *(float4*)&As[ar][ak]      = pa0;
    *(float4*)&As[ar + 64][ak] = pa1;
    *(float4*)&Ws[wk][wc]      = pw;
    __syncthreads();

    for (int kt = 0; kt < nk; kt++) {
        if (kt + 1 < nk) {
            const int kb = (kt + 1) << 4;
            const float* src; int lda, kk;
            if (kb < kSplit) { src = A0; lda = kSplit;     kk = kb; }
            else             { src = A1; lda = K - kSplit; kk = kb - kSplit; }
            pa0 = *(const float4*)(src + (size_t)(m0 + ar) * lda + kk + ak);
            pa1 = *(const float4*)(src + (size_t)(m0 + ar + 64) * lda + kk + ak);
            pw  = *(const float4*)(W + (size_t)(kb + wk) * N + n0 + wc);
        }
#pragma unroll
        for (int k4 = 0; k4 < 4; k4++) {
            float4 av4[8];
#pragma unroll
            for (int i = 0; i < 8; i++)
                av4[i] = *(const float4*)&As[ty * 8 + i][k4 * 4];
#pragma unroll
            for (int kk = 0; kk < 4; kk++) {
                ulonglong2 w2 = *(const ulonglong2*)&Ws[k4 * 4 + kk][tx * 4];
#pragma unroll
                for (int i = 0; i < 8; i++) {
                    ULL a2 = bcast2(((const float*)&av4[i])[kk]);
                    fma2(acc2[i][0], a2, w2.x);
                    fma2(acc2[i][1], a2, w2.y);
                }
            }
        }
        __syncthreads();
        if (kt + 1 < nk) {
            *(float4*)&As[ar][ak]      = pa0;
            *(float4*)&As[ar + 64][ak] = pa1;
            *(float4*)&Ws[wk][wc]      = pw;
        }
        __syncthreads();
    }

#pragma unroll
    for (int i = 0; i < 8; i++) {
        const int m = m0 + ty * 8 + i;
        float2 u0 = unpack2(acc2[i][0]);
        float2 u1 = unpack2(acc2[i][1]);
        float v0 = u0.x, v1 = u0.y, v2 = u1.x, v3 = u1.y;
        if (RELU) {
            v0 = fmaxf(v0, 0.f); v1 = fmaxf(v1, 0.f);
            v2 = fmaxf(v2, 0.f); v3 = fmaxf(v3, 0.f);
        }
        if (rotary) {
            const int c0 = n0 + tx * 4;
            const float* pr = pe + ((size_t)m * 256 + c0) * 2;
            float4 p0 = *(const float4*)pr;
            float4 p1 = *(const float4*)(pr + 4);
            float e = v0, o = v1;
            v0 = e * p0.x - o * p0.y;
            v1 = o * p0.z + e * p0.w;
            e = v2; o = v3;
            v2 = e * p1.x - o * p1.y;
            v3 = o * p1.z + e * p1.w;
        }
        *(float4*)(C + (size_t)m * N + n0 + tx * 4) = make_float4(v0, v1, v2, v3);
    }
}

template <bool RELU, bool ROTARY>
__global__ __launch_bounds__(256) void gemm_k(
    const float* __restrict__ A0, const float* __restrict__ A1, int kSplit,
    const float* __restrict__ W, const float* __restrict__ pe,
    float* __restrict__ C, int M, int N, int K)
{
    __shared__ __align__(16) float As[128][16];
    __shared__ __align__(16) float Ws[16][64];
    gemm_body<RELU>(A0, A1, kSplit, W, pe, ROTARY, C, N, K, As, Ws);
}

// Fused Q/K/V projection: z selects {A, W, pe, C, rotary}. 384 CTAs.
__global__ __launch_bounds__(256) void qkv_k(
    const float* __restrict__ x, const float* __restrict__ src,
    const float* __restrict__ xpe, const float* __restrict__ spe,
    const float* __restrict__ Wq, const float* __restrict__ Wk,
    const float* __restrict__ Wv,
    float* __restrict__ Qb, float* __restrict__ Kb, float* __restrict__ Vb)
{
    __shared__ __align__(16) float As[128][16];
    __shared__ __align__(16) float Ws[16][64];
    const int z = blockIdx.z;
    const float* A  = (z == 0) ? x   : src;
    const float* W  = (z == 0) ? Wq  : (z == 1 ? Wk : Wv);
    const float* pe = (z == 0) ? xpe : spe;
    float* C        = (z == 0) ? Qb  : (z == 1 ? Kb : Vb);
    gemm_body<false>(A, nullptr, 256, W, pe, z < 2, C, 256, 256, As, Ws);
}

// ---------------- GEMM + fused LayerNorm (split columns: conflict-free) ---
// Thread tx owns cols {tx*4..+3, 128+tx*4..+3}: each LDS.128 phase is
// 128B-contiguous (no 2-way conflicts). Pure column permutation.
__global__ __launch_bounds__(256) void gemm_ln_k(
    const float* __restrict__ A, const float* __restrict__ W, int K,
    const float* __restrict__ g, const float* __restrict__ b,
    const float* __restrict__ resid, float* __restrict__ out)
{
    __shared__ __align__(16) float As[32][16];
    __shared__ __align__(16) float Ws[16][256];

    const int tid = threadIdx.x;
    const int tx = tid & 31;
    const int ty = tid >> 5;
    const int m0 = blockIdx.x * 32;

    ULL acc2[4][4];
#pragma unroll
    for (int i = 0; i < 4; i++)
#pragma unroll
        for (int j = 0; j < 4; j++) acc2[i][j] = 0ull;

    const int nk = K >> 4;
    const int ar = tid >> 2, ak = (tid & 3) * 4;

    float4 pa, pw[4];
    if (tid < 128)
        pa = *(const float4*)(A + (size_t)(m0 + ar) * K + ak);
#pragma unroll
    for (int it = 0; it < 4; it++) {
        int gidx = tid + it * 256;
        int wr = gidx >> 6, wc = (gidx & 63) * 4;
        pw[it] = *(const float4*)(W + (size_t)wr * 256 + wc);
    }
    if (tid < 128) *(float4*)&As[ar][ak] = pa;
#pragma unroll
    for (int it = 0; it < 4; it++) {
        int gidx = tid + it * 256;
        int wr = gidx >> 6, wc = (gidx & 63) * 4;
        *(float4*)&Ws[wr][wc] = pw[it];
    }
    __syncthreads();

    for (int kt = 0; kt < nk; kt++) {
        if (kt + 1 < nk) {
            const int kb = (kt + 1) << 4;
            if (tid < 128)
                pa = *(const float4*)(A + (size_t)(m0 + ar) * K + kb + ak);
#pragma unroll
            for (int it = 0; it < 4; it++) {
                int gidx = tid + it * 256;
                int wr = gidx >> 6, wc = (gidx & 63) * 4;
                pw[it] = *(const float4*)(W + (size_t)(kb + wr) * 256 + wc);
            }
        }
#pragma unroll
        for (int k4 = 0; k4 < 4; k4++) {
            float4 av4[4];
#pragma unroll
            for (int i = 0; i < 4; i++)
                av4[i] = *(const float4*)&As[ty * 4 + i][k4 * 4];
#pragma unroll
            for (int kk = 0; kk < 4; kk++) {
                const float* wrow = &Ws[k4 * 4 + kk][0];
                ulonglong2 wA = *(const ulonglong2*)(wrow + tx * 4);        // cols tx*4..+3
                ulonglong2 wB = *(const ulonglong2*)(wrow + 128 + tx * 4);  // cols 128+tx*4..+3
#pragma unroll
                for (int i = 0; i < 4; i++) {
                    ULL a2 = bcast2(((const float*)&av4[i])[kk]);
                    fma2(acc2[i][0], a2, wA.x);
                    fma2(acc2[i][1], a2, wA.y);
                    fma2(acc2[i][2], a2, wB.x);
                    fma2(acc2[i][3], a2, wB.y);
                }
            }
        }
        __syncthreads();
        if (kt + 1 < nk) {
            if (tid < 128) *(float4*)&As[ar][ak] = pa;
#pragma unroll
            for (int it = 0; it < 4; it++) {
                int gidx = tid + it * 256;
                int wr = gidx >> 6, wc = (gidx & 63) * 4;
                *(float4*)&Ws[wr][wc] = pw[it];
            }
        }
        __syncthreads();
    }

    const int c0 = tx * 4, c1 = 128 + tx * 4;
    const float4 gA = *(const float4*)(g + c0);
    const float4 gB = *(const float4*)(g + c1);
    const float4 bA = *(const float4*)(b + c0);
    const float4 bB = *(const float4*)(b + c1);

#pragma unroll
    for (int i = 0; i < 4; i++) {
        const int m = m0 + ty * 4 + i;
        float v[8];
        float2 u0 = unpack2(acc2[i][0]); v[0] = u0.x; v[1] = u0.y;
        float2 u1 = unpack2(acc2[i][1]); v[2] = u1.x; v[3] = u1.y;
        float2 u2 = unpack2(acc2[i][2]); v[4] = u2.x; v[5] = u2.y;
        float2 u3 = unpack2(acc2[i][3]); v[6] = u3.x; v[7] = u3.y;

        float s = 0.f, ss = 0.f;
#pragma unroll
        for (int j = 0; j < 8; j++) { s += v[j]; ss += v[j] * v[j]; }
#pragma unroll
        for (int off = 16; off; off >>= 1) {
            s  += __shfl_xor_sync(0xffffffffu, s, off);
            ss += __shfl_xor_sync(0xffffffffu, ss, off);
        }
        const float mu  = s * (1.f / 256.f);
        const float var = ss * (1.f / 256.f) - mu * mu;
        const float rs  = rsqrtf(var + 1e-5f);

        float r0 = (v[0] - mu) * rs * gA.x + bA.x;
        float r1 = (v[1] - mu) * rs * gA.y + bA.y;
        float r2 = (v[2] - mu) * rs * gA.z + bA.z;
        float r3 = (v[3] - mu) * rs * gA.w + bA.w;
        float r4 = (v[4] - mu) * rs * gB.x + bB.x;
        float r5 = (v[5] - mu) * rs * gB.y + bB.y;
        float r6 = (v[6] - mu) * rs * gB.z + bB.z;
        float r7 = (v[7] - mu) * rs * gB.w + bB.w;

        if (resid) {
            const float* rp = resid + (size_t)m * 256;
            float4 x0 = *(const float4*)(rp + c0);
            float4 x1 = *(const float4*)(rp + c1);
            r0 += x0.x; r1 += x0.y; r2 += x0.z; r3 += x0.w;
            r4 += x1.x; r5 += x1.y; r6 += x1.z; r7 += x1.w;
        }
        float* dst = out + (size_t)m * 256;
        *(float4*)(dst + c0) = make_float4(r0, r1, r2, r3);
        *(float4*)(dst + c1) = make_float4(r4, r5, r6, r7);
    }
}

// ---------------- FlashAttention (fp32, f32x2, Q-tile 64, 2 CTAs/SM) -----
// 64 queries/CTA, 128-key blocks, 256 threads. smem = 112 KB -> 2 CTAs/SM
// (4 warps/SMSP for latency hiding). QK: 4 rows x 8 split cols; PV: 2 rows
// x 8 split cols. No-max softmax (S bounded), per-lane denominator.
__global__ __launch_bounds__(256, 2) void attn_k(
    const float* __restrict__ Q, const float* __restrict__ Kg,
    const float* __restrict__ Vg, float* __restrict__ O)
{
    extern __shared__ __align__(16) float sm[];
    float* Qs   = sm;                    // [64][64]
    float* Vs   = Qs + 64 * 64;          // [128][64]
    float* KsT  = Vs + 128 * 64;         // [64][128]  (d, s)
    float* Ps   = KsT + 64 * 128;        // [64][128]
    float* sden = Ps + 64 * 128;         // [64]

    const int tid = threadIdx.x;
    const int txq = tid & 15;   // QK col group: {txq*4, 64+txq*4}
    const int tyq = tid >> 4;   // 0..15, rows *4
    const int txv = tid & 7;    // PV col group: {txv*4, 32+txv*4}
    const int tyv = tid >> 3;   // 0..31, rows *2
    const int q0 = blockIdx.x * 64;
    const int b = blockIdx.y >> 2;
    const int h = blockIdx.y & 3;

    const float* Qp = Q  + ((size_t)b * 2048 + q0) * 256 + h * 64;
    const float* Kp = Kg + (size_t)b * 2048 * 256 + h * 64;
    const float* Vp = Vg + (size_t)b * 2048 * 256 + h * 64;

    const float QSCALE = 0.18033688011112042f;  // 0.125 * log2(e)

    // ---- prologue: Q (scaled) -------------------------------------------
#pragma unroll
    for (int it = 0; it < 4; it++) {
        int g = tid + it * 256;
        int r = g >> 4, c = (g & 15) << 2;
        float4 q = *(const float4*)(Qp + (size_t)r * 256 + c);
        *(float4*)&Qs[r * 64 + c] =
            make_float4(q.x * QSCALE, q.y * QSCALE, q.z * QSCALE, q.w * QSCALE);
    }

    ULL o2[2][4];
    float den[4];
#pragma unroll
    for (int i = 0; i < 2; i++)
#pragma unroll
        for (int j = 0; j < 4; j++) o2[i][j] = 0ull;
#pragma unroll
    for (int i = 0; i < 4; i++) den[i] = 0.f;

    for (int kt = 0; kt < 16; kt++) {
        __syncthreads();   // prev iter done with KsT/Vs/Ps (and Qs stored)

        // ---- load K (transposed) + V tiles
        const float* Kb = Kp + (size_t)kt * 128 * 256;
        const float* Vb = Vp + (size_t)kt * 128 * 256;
#pragma unroll
        for (int it = 0; it < 8; it++) {
            int g = tid + it * 256;
            int s = g & 127, dg = g >> 7;   // dg 0..7 -> covers d 0..31? no: g<2048, dg 0..7
            float4 kv = *(const float4*)(Kb + (size_t)s * 256 + dg * 4 + ((it & 1) ? 32 : 0));
            // NOTE: see remap below
            (void)kv;
            break;
        }
        // K: 128 s x 64 d = 2048 float4; g in [0,2048): s = g & 127, dgrp = g >> 7 (0..15)
#pragma unroll
        for (int it = 0; it < 8; it++) {
            int g = tid + it * 256;
            int s = g & 127, dg = g >> 7;
            float4 kv = *(const float4*)(Kb + (size_t)s * 256 + dg * 4);
            KsT[(dg * 4 + 0) * 128 + s] = kv.x;
            KsT[(dg * 4 + 1) * 128 + s] = kv.y;
            KsT[(dg * 4 + 2) * 128 + s] = kv.z;
            KsT[(dg * 4 + 3) * 128 + s] = kv.w;
        }
        // V: 128 s x 64 d: g in [0,2048): s = g >> 4, c = (g & 15) * 4
#pragma unroll
        for (int it = 0; it < 8; it++) {
            int g = tid + it * 256;
            int s = g >> 4, c = (g & 15) << 2;
            *(float4*)&Vs[s * 64 + c] = *(const float4*)(Vb + (size_t)s * 256 + c);
        }
        __syncthreads();

        // ---- S = Q @ K^T : 4 rows x 8 cols (split {txq*4, 64+txq*4})
        ULL s2[4][4];
#pragma unroll
        for (int i = 0; i < 4; i++)
#pragma unroll
            for (int j = 0; j < 4; j++) s2[i][j] = 0ull;

#pragma unroll
        for (int d4 = 0; d4 < 16; d4++) {
            float4 q4[4];
#pragma unroll
            for (int i = 0; i < 4; i++)
                q4[i] = *(const float4*)&Qs[(tyq * 4 + i) * 64 + d4 * 4];
#pragma unroll
            for (int dd = 0; dd < 4; dd++) {
                const float* krow = &KsT[(d4 * 4 + dd) * 128];
                ulonglong2 kA = *(const ulonglong2*)(krow + txq * 4);
                ulonglong2 kB = *(const ulonglong2*)(krow + 64 + txq * 4);
#pragma unroll
                for (int i = 0; i < 4; i++) {
                    ULL qq = bcast2(((const float*)&q4[i])[dd]);
                    fma2(s2[i][0], qq, kA.x);
                    fma2(s2[i][1], qq, kA.y);
                    fma2(s2[i][2], qq, kB.x);
                    fma2(s2[i][3], qq, kB.y);
                }
            }
        }

        // ---- softmax without max-shift: p = 2^S, den += sum(p)
#pragma unroll
        for (int i = 0; i < 4; i++) {
            float p[8];
            float2 t0 = unpack2(s2[i][0]); p[0] = ex2(t0.x); p[1] = ex2(t0.y);
            float2 t1 = unpack2(s2[i][1]); p[2] = ex2(t1.x); p[3] = ex2(t1.y);
            float2 t2 = unpack2(s2[i][2]); p[4] = ex2(t2.x); p[5] = ex2(t2.y);
            float2 t3 = unpack2(s2[i][3]); p[6] = ex2(t3.x); p[7] = ex2(t3.y);
            den[i] += ((p[0] + p[1]) + (p[2] + p[3]))
                    + ((p[4] + p[5]) + (p[6] + p[7]));
            float* pr = &Ps[(tyq * 4 + i) * 128];
            *(float4*)(pr + txq * 4)      = make_float4(p[0], p[1], p[2], p[3]);
            *(float4*)(pr + 64 + txq * 4) = make_float4(p[4], p[5], p[6], p[7]);
        }
        __syncthreads();   // Ps visible; all warps done with KsT

        // ---- O += P @ V : 2 rows x 8 cols (split {txv*4, 32+txv*4})
#pragma unroll
        for (int k4 = 0; k4 < 32; k4++) {
            float4 p4[2];
#pragma unroll
            for (int i = 0; i < 2; i++)
                p4[i] = *(const float4*)&Ps[(tyv * 2 + i) * 128 + k4 * 4];
#pragma unroll
            for (int kk = 0; kk < 4; kk++) {
                const float* vrow = &Vs[(k4 * 4 + kk) * 64];
                ulonglong2 vA = *(const ulonglong2*)(vrow + txv * 4);
                ulonglong2 vB = *(const ulonglong2*)(vrow + 32 + txv * 4);
#pragma unroll
                for (int i = 0; i < 2; i++) {
                    ULL pp = bcast2(((const float*)&p4[i])[kk]);
                    fma2(o2[i][0], pp, vA.x);
                    fma2(o2[i][1], pp, vA.y);
                    fma2(o2[i][2], pp, vB.x);
                    fma2(o2[i][3], pp, vB.y);
                }
            }
        }
    }

    // ---- denominator: reduce across the 16-lane row group, stash in smem
#pragma unroll
    for (int i = 0; i < 4; i++) {
#pragma unroll
        for (int off = 8; off; off >>= 1)
            den[i] += __shfl_xor_sync(0xffffffffu, den[i], off);
    }
    if (txq == 0) {
#pragma unroll
        for (int i = 0; i < 4; i++) sden[tyq * 4 + i] = den[i];
    }
    __syncthreads();

    // ---- epilogue (PV map): O / den
    float* Op = O + ((size_t)b * 2048 + q0) * 256 + h * 64;
#pragma unroll
    for (int i = 0; i < 2; i++) {
        const int row = tyv * 2 + i;
        const float inv = 1.f / sden[row];
        float2 a0 = unpack2(o2[i][0]);
        float2 a1 = unpack2(o2[i][1]);
        float2 a2 = unpack2(o2[i][2]);
        float2 a3 = unpack2(o2[i][3]);
        float* dst = Op + (size_t)row * 256;
        *(float4*)(dst + txv * 4) =
            make_float4(a0.x * inv, a0.y * inv, a1.x * inv, a1.y * inv);
        *(float4*)(dst + 32 + txv * 4) =
            make_float4(a2.x * inv, a2.y * inv, a3.x * inv, a3.y * inv);
    }
}

// ---------------- launch -------------------------------------------------
extern "C" void kernel_launch(void* const* d_in, const int* in_sizes, int n_in,
                              void* d_out, int out_size)
{
    (void)in_sizes; (void)n_in; (void)out_size;
    const float* x   = (const float*)d_in[0];
    const float* src = (const float*)d_in[1];
    const float* xpe = (const float*)d_in[2];
    const float* spe = (const float*)d_in[3];
    const float* Wq  = (const float*)d_in[4];
    const float* Wk  = (const float*)d_in[5];
    const float* Wv  = (const float*)d_in[6];
    const float* Wm  = (const float*)d_in[7];
    const float* W1  = (const float*)d_in[8];
    const float* W2  = (const float*)d_in[9];
    const float* g1  = (const float*)d_in[10];
    const float* b1  = (const float*)d_in[11];
    const float* g2  = (const float*)d_in[12];
    const float* b2  = (const float*)d_in[13];
    float* out = (float*)d_out;

    float *Qb, *Kb, *Vb, *Ob, *Msg, *Hb;
    cudaGetSymbolAddress((void**)&Qb,  g_Q);
    cudaGetSymbolAddress((void**)&Kb,  g_K);
    cudaGetSymbolAddress((void**)&Vb,  g_V);
    cudaGetSymbolAddress((void**)&Ob,  g_O);
    cudaGetSymbolAddress((void**)&Msg, g_Msg);
    cudaGetSymbolAddress((void**)&Hb,  g_H);

    const int ATTN_SMEM = (64 * 64 + 128 * 64 + 64 * 128 + 64 * 128 + 64) * 4; // 114944 B
    cudaFuncSetAttribute(attn_k, cudaFuncAttributeMaxDynamicSharedMemorySize, ATTN_SMEM);

    const dim3 blk(256);
    // fused Q/K/V projections (rotary on Q,K)
    qkv_k<<<dim3(4, 32, 3), blk>>>(x, src, xpe, spe, Wq, Wk, Wv, Qb, Kb, Vb);
    // attention: 256 CTAs, 2/SM
    attn_k<<<dim3(32, 8), blk, ATTN_SMEM>>>(Qb, Kb, Vb, Ob);
    // message = LN(O @ Wm)   (fused)
    gemm_ln_k<<<128, blk>>>(Ob, Wm, 256, g1, b1, nullptr, Msg);
    // h = relu(concat(x, message) @ W1)
    gemm_k<true, false><<<dim3(8, 32), blk>>>(x, Msg, 256, W1, nullptr, Hb, 4096, 512, 512);
    // out = x + LN(h @ W2)   (fused)
    gemm_ln_k<<<128, blk>>>(Hb, W2, 512, g2, b2, x, out);
}

// round 12
// speedup vs baseline: 1.2148x; 1.2148x over previous
#include <cuda_runtime.h>
#include <math.h>

typedef unsigned long long ULL;

// ---------------- f32x2 packed-math helpers (sm_100+) --------------------
__device__ __forceinline__ ULL bcast2(float v) {
    ULL r; asm("mov.b64 %0, {%1, %1};" : "=l"(r) : "f"(v)); return r;
}
__device__ __forceinline__ void fma2(ULL& d, ULL a, ULL b) {
    asm("fma.rn.f32x2 %0, %1, %2, %0;" : "+l"(d) : "l"(a), "l"(b));
}
__device__ __forceinline__ float2 unpack2(ULL v) {
    float2 f; asm("mov.b64 {%0, %1}, %2;" : "=f"(f.x), "=f"(f.y) : "l"(v)); return f;
}
__device__ __forceinline__ float ex2(float x) {
    float r; asm("ex2.approx.f32 %0, %1;" : "=f"(r) : "f"(x)); return r;
}

// ---------------- scratch buffers (no allocation allowed) ----------------
__device__ float g_Q[4096 * 256];
__device__ float g_K[4096 * 256];
__device__ float g_V[4096 * 256];
__device__ float g_O[4096 * 256];
__device__ float g_Msg[4096 * 256];
__device__ float g_H[4096 * 512];

// ---------------- GEMM core (f32x2) — R7/R10 proven version ---------------
template <bool RELU>
__device__ __forceinline__ void gemm_body(
    const float* __restrict__ A0, const float* __restrict__ A1, int kSplit,
    const float* __restrict__ W, const float* __restrict__ pe, bool rotary,
    float* __restrict__ C, int N, int K,
    float (*As)[16], float (*Ws)[64])
{
    const int tid = threadIdx.x;
    const int tx = tid & 15;
    const int ty = tid >> 4;
    const int m0 = blockIdx.y * 128;
    const int n0 = blockIdx.x * 64;

    const int ar = tid >> 2;
    const int ak = (tid & 3) * 4;
    const int wk = tid >> 4;
    const int wc = (tid & 15) * 4;

    ULL acc2[8][2];
#pragma unroll
    for (int i = 0; i < 8; i++) { acc2[i][0] = 0ull; acc2[i][1] = 0ull; }

    const int nk = K >> 4;
    float4 pa0, pa1, pw;

    pa0 = *(const float4*)(A0 + (size_t)(m0 + ar) * kSplit + ak);
    pa1 = *(const float4*)(A0 + (size_t)(m0 + ar + 64) * kSplit + ak);
    pw  = *(const float4*)(W + (size_t)wk * N + n0 + wc);
    *(float4*)&As[ar][ak]      = pa0;
    *(float4*)&As[ar + 64][ak] = pa1;
    *(float4*)&Ws[wk][wc]      = pw;
    __syncthreads();

    for (int kt = 0; kt < nk; kt++) {
        if (kt + 1 < nk) {
            const int kb = (kt + 1) << 4;
            const float* src; int lda, kk;
            if (kb < kSplit) { src = A0; lda = kSplit;     kk = kb; }
            else             { src = A1; lda = K - kSplit; kk = kb - kSplit; }
            pa0 = *(const float4*)(src + (size_t)(m0 + ar) * lda + kk + ak);
            pa1 = *(const float4*)(src + (size_t)(m0 + ar + 64) * lda + kk + ak);
            pw  = *(const float4*)(W + (size_t)(kb + wk) * N + n0 + wc);
        }
#pragma unroll
        for (int k4 = 0; k4 < 4; k4++) {
            float4 av4[8];
#pragma unroll
            for (int i = 0; i < 8; i++)
                av4[i] = *(const float4*)&As[ty * 8 + i][k4 * 4];
#pragma unroll
            for (int kk = 0; kk < 4; kk++) {
                ulonglong2 w2 = *(const ulonglong2*)&Ws[k4 * 4 + kk][tx * 4];
#pragma unroll
                for (int i = 0; i < 8; i++) {
                    ULL a2 = bcast2(((const float*)&av4[i])[kk]);
                    fma2(acc2[i][0], a2, w2.x);
                    fma2(acc2[i][1], a2, w2.y);
                }
            }
        }
        __syncthreads();
        if (kt + 1 < nk) {
            *(float4*)&As[ar][ak]      = pa0;
            *(float4*)&As[ar + 64][ak] = pa1;
            *(float4*)&Ws[wk][wc]      = pw;
        }
        __syncthreads();
    }

#pragma unroll
    for (int i = 0; i < 8; i++) {
        const int m = m0 + ty * 8 + i;
        float2 u0 = unpack2(acc2[i][0]);
        float2 u1 = unpack2(acc2[i][1]);
        float v0 = u0.x, v1 = u0.y, v2 = u1.x, v3 = u1.y;
        if (RELU) {
            v0 = fmaxf(v0, 0.f); v1 = fmaxf(v1, 0.f);
            v2 = fmaxf(v2, 0.f); v3 = fmaxf(v3, 0.f);
        }
        if (rotary) {
            const int c0 = n0 + tx * 4;
            const float* pr = pe + ((size_t)m * 256 + c0) * 2;
            float4 p0 = *(const float4*)pr;
            float4 p1 = *(const float4*)(pr + 4);
            float e = v0, o = v1;
            v0 = e * p0.x - o * p0.y;
            v1 = o * p0.z + e * p0.w;
            e = v2; o = v3;
            v2 = e * p1.x - o * p1.y;
            v3 = o * p1.z + e * p1.w;
        }
        *(float4*)(C + (size_t)m * N + n0 + tx * 4) = make_float4(v0, v1, v2, v3);
    }
}

template <bool RELU, bool ROTARY>
__global__ __launch_bounds__(256) void gemm_k(
    const float* __restrict__ A0, const float* __restrict__ A1, int kSplit,
    const float* __restrict__ W, const float* __restrict__ pe,
    float* __restrict__ C, int M, int N, int K)
{
    __shared__ __align__(16) float As[128][16];
    __shared__ __align__(16) float Ws[16][64];
    gemm_body<RELU>(A0, A1, kSplit, W, pe, ROTARY, C, N, K, As, Ws);
}

// Fused Q/K/V projection: z selects {A, W, pe, C, rotary}. 384 CTAs.
__global__ __launch_bounds__(256) void qkv_k(
    const float* __restrict__ x, const float* __restrict__ src,
    const float* __restrict__ xpe, const float* __restrict__ spe,
    const float* __restrict__ Wq, const float* __restrict__ Wk,
    const float* __restrict__ Wv,
    float* __restrict__ Qb, float* __restrict__ Kb, float* __restrict__ Vb)
{
    __shared__ __align__(16) float As[128][16];
    __shared__ __align__(16) float Ws[16][64];
    const int z = blockIdx.z;
    const float* A  = (z == 0) ? x   : src;
    const float* W  = (z == 0) ? Wq  : (z == 1 ? Wk : Wv);
    const float* pe = (z == 0) ? xpe : spe;
    float* C        = (z == 0) ? Qb  : (z == 1 ? Kb : Vb);
    gemm_body<false>(A, nullptr, 256, W, pe, z < 2, C, 256, 256, As, Ws);
}

// ---------------- GEMM + fused LayerNorm (split columns, R11-proven) ------
__global__ __launch_bounds__(256) void gemm_ln_k(
    const float* __restrict__ A, const float* __restrict__ W, int K,
    const float* __restrict__ g, const float* __restrict__ b,
    const float* __restrict__ resid, float* __restrict__ out)
{
    __shared__ __align__(16) float As[32][16];
    __shared__ __align__(16) float Ws[16][256];

    const int tid = threadIdx.x;
    const int tx = tid & 31;
    const int ty = tid >> 5;
    const int m0 = blockIdx.x * 32;

    ULL acc2[4][4];
#pragma unroll
    for (int i = 0; i < 4; i++)
#pragma unroll
        for (int j = 0; j < 4; j++) acc2[i][j] = 0ull;

    const int nk = K >> 4;
    const int ar = tid >> 2, ak = (tid & 3) * 4;

    float4 pa, pw[4];
    if (tid < 128)
        pa = *(const float4*)(A + (size_t)(m0 + ar) * K + ak);
#pragma unroll
    for (int it = 0; it < 4; it++) {
        int gidx = tid + it * 256;
        int wr = gidx >> 6, wc = (gidx & 63) * 4;
        pw[it] = *(const float4*)(W + (size_t)wr * 256 + wc);
    }
    if (tid < 128) *(float4*)&As[ar][ak] = pa;
#pragma unroll
    for (int it = 0; it < 4; it++) {
        int gidx = tid + it * 256;
        int wr = gidx >> 6, wc = (gidx & 63) * 4;
        *(float4*)&Ws[wr][wc] = pw[it];
    }
    __syncthreads();

    for (int kt = 0; kt < nk; kt++) {
        if (kt + 1 < nk) {
            const int kb = (kt + 1) << 4;
            if (tid < 128)
                pa = *(const float4*)(A + (size_t)(m0 + ar) * K + kb + ak);
#pragma unroll
            for (int it = 0; it < 4; it++) {
                int gidx = tid + it * 256;
                int wr = gidx >> 6, wc = (gidx & 63) * 4;
                pw[it] = *(const float4*)(W + (size_t)(kb + wr) * 256 + wc);
            }
        }
#pragma unroll
        for (int k4 = 0; k4 < 4; k4++) {
            float4 av4[4];
#pragma unroll
            for (int i = 0; i < 4; i++)
                av4[i] = *(const float4*)&As[ty * 4 + i][k4 * 4];
#pragma unroll
            for (int kk = 0; kk < 4; kk++) {
                const float* wrow = &Ws[k4 * 4 + kk][0];
                ulonglong2 wA = *(const ulonglong2*)(wrow + tx * 4);
                ulonglong2 wB = *(const ulonglong2*)(wrow + 128 + tx * 4);
#pragma unroll
                for (int i = 0; i < 4; i++) {
                    ULL a2 = bcast2(((const float*)&av4[i])[kk]);
                    fma2(acc2[i][0], a2, wA.x);
                    fma2(acc2[i][1], a2, wA.y);
                    fma2(acc2[i][2], a2, wB.x);
                    fma2(acc2[i][3], a2, wB.y);
                }
            }
        }
        __syncthreads();
        if (kt + 1 < nk) {
            if (tid < 128) *(float4*)&As[ar][ak] = pa;
#pragma unroll
            for (int it = 0; it < 4; it++) {
                int gidx = tid + it * 256;
                int wr = gidx >> 6, wc = (gidx & 63) * 4;
                *(float4*)&Ws[wr][wc] = pw[it];
            }
        }
        __syncthreads();
    }

    const int c0 = tx * 4, c1 = 128 + tx * 4;
    const float4 gA = *(const float4*)(g + c0);
    const float4 gB = *(const float4*)(g + c1);
    const float4 bA = *(const float4*)(b + c0);
    const float4 bB = *(const float4*)(b + c1);

#pragma unroll
    for (int i = 0; i < 4; i++) {
        const int m = m0 + ty * 4 + i;
        float v[8];
        float2 u0 = unpack2(acc2[i][0]); v[0] = u0.x; v[1] = u0.y;
        float2 u1 = unpack2(acc2[i][1]); v[2] = u1.x; v[3] = u1.y;
        float2 u2 = unpack2(acc2[i][2]); v[4] = u2.x; v[5] = u2.y;
        float2 u3 = unpack2(acc2[i][3]); v[6] = u3.x; v[7] = u3.y;

        float s = 0.f, ss = 0.f;
#pragma unroll
        for (int j = 0; j < 8; j++) { s += v[j]; ss += v[j] * v[j]; }
#pragma unroll
        for (int off = 16; off; off >>= 1) {
            s  += __shfl_xor_sync(0xffffffffu, s, off);
            ss += __shfl_xor_sync(0xffffffffu, ss, off);
        }
        const float mu  = s * (1.f / 256.f);
        const float var = ss * (1.f / 256.f) - mu * mu;
        const float rs  = rsqrtf(var + 1e-5f);

        float r0 = (v[0] - mu) * rs * gA.x + bA.x;
        float r1 = (v[1] - mu) * rs * gA.y + bA.y;
        float r2 = (v[2] - mu) * rs * gA.z + bA.z;
        float r3 = (v[3] - mu) * rs * gA.w + bA.w;
        float r4 = (v[4] - mu) * rs * gB.x + bB.x;
        float r5 = (v[5] - mu) * rs * gB.y + bB.y;
        float r6 = (v[6] - mu) * rs * gB.z + bB.z;
        float r7 = (v[7] - mu) * rs * gB.w + bB.w;

        if (resid) {
            const float* rp = resid + (size_t)m * 256;
            float4 x0 = *(const float4*)(rp + c0);
            float4 x1 = *(const float4*)(rp + c1);
            r0 += x0.x; r1 += x0.y; r2 += x0.z; r3 += x0.w;
            r4 += x1.x; r5 += x1.y; r6 += x1.z; r7 += x1.w;
        }
        float* dst = out + (size_t)m * 256;
        *(float4*)(dst + c0) = make_float4(r0, r1, r2, r3);
        *(float4*)(dst + c1) = make_float4(r4, r5, r6, r7);
    }
}

// ---------------- FlashAttention (fp32, f32x2, mov-minimized) -------------
// R10 structure (128 q/CTA, 128-key blocks, 256 threads), two changes:
//  1. Q stored pre-duplicated as packed f32x2 (ULL) in smem -> QK inner loop
//     loads the broadcast operand with LDS.64 (LSU pipe) instead of mov.b64
//     (FMA pipe). Removes all 512 QK movs per thread per block.
//  2. PV remapped to 4 rows x 8 split cols per thread (mov:fma2 = 1:4),
//     halving PV movs. Denominator handed over via sden smem array.
// Per-element FMA order identical to R10 -> same rel_err.
__global__ __launch_bounds__(256) void attn_k(
    const float* __restrict__ Q, const float* __restrict__ Kg,
    const float* __restrict__ Vg, float* __restrict__ O)
{
    extern __shared__ __align__(16) float sm[];
    ULL*   Qd   = (ULL*)sm;                       // [128][64] packed pairs (64 KB)
    float* Vs   = (float*)(Qd + 128 * 64);        // [128][64]  (32 KB)
    float* KsT  = Vs + 128 * 64;                  // [64][128]  (d, s) (32 KB)
    float* Ps   = KsT + 64 * 128;                 // [128][128] (64 KB)
    float* sden = Ps + 128 * 128;                 // [128]

    const int tid = threadIdx.x;
    const int txq = tid & 15;    // QK cols {txq*4..+3, 64+txq*4..+3}
    const int tyq = tid >> 4;    // QK rows tyq*8..+7
    const int txv = tid & 7;     // PV cols {txv*4..+3, 32+txv*4..+3}
    const int tyv = tid >> 3;    // PV rows tyv*4..+3
    const int q0 = blockIdx.x * 128;
    const int b = blockIdx.y >> 2;
    const int h = blockIdx.y & 3;

    const float* Qp = Q  + ((size_t)b * 2048 + q0) * 256 + h * 64;
    const float* Kp = Kg + (size_t)b * 2048 * 256 + h * 64;
    const float* Vp = Vg + (size_t)b * 2048 * 256 + h * 64;

    const float QSCALE = 0.18033688011112042f;  // 0.125 * log2(e)

    // ---- prologue: Q scaled + duplicated into packed pairs ---------------
#pragma unroll
    for (int it = 0; it < 8; it++) {
        int g = tid + it * 256;
        int r = g >> 4, c = (g & 15) << 2;
        float4 q = *(const float4*)(Qp + (size_t)r * 256 + c);
        ULL* dst = &Qd[r * 64 + c];
        ulonglong2 w0, w1;
        w0.x = bcast2(q.x * QSCALE); w0.y = bcast2(q.y * QSCALE);
        w1.x = bcast2(q.z * QSCALE); w1.y = bcast2(q.w * QSCALE);
        *(ulonglong2*)dst       = w0;
        *(ulonglong2*)(dst + 2) = w1;
    }
    // ---- K0 (transposed) + V0 --------------------------------------------
#pragma unroll
    for (int it = 0; it < 8; it++) {
        int g = tid + it * 256;
        int s = g & 127, dg = g >> 7;
        float4 kv = *(const float4*)(Kp + (size_t)s * 256 + dg * 4);
        KsT[(dg * 4 + 0) * 128 + s] = kv.x;
        KsT[(dg * 4 + 1) * 128 + s] = kv.y;
        KsT[(dg * 4 + 2) * 128 + s] = kv.z;
        KsT[(dg * 4 + 3) * 128 + s] = kv.w;
    }
#pragma unroll
    for (int it = 0; it < 8; it++) {
        int g = tid + it * 256;
        int s = g >> 4, c = (g & 15) << 2;
        *(float4*)&Vs[s * 64 + c] = *(const float4*)(Vp + (size_t)s * 256 + c);
    }
    __syncthreads();

    ULL o2[4][4];
    float den[8];
#pragma unroll
    for (int i = 0; i < 4; i++)
#pragma unroll
        for (int j = 0; j < 4; j++) o2[i][j] = 0ull;
#pragma unroll
    for (int i = 0; i < 8; i++) den[i] = 0.f;

    for (int kt = 0; kt < 16; kt++) {
        // ---- S = Q @ K^T : 8 rows x 8 split cols; Q operand via LDS.64
        ULL s2[8][4];
#pragma unroll
        for (int i = 0; i < 8; i++)
#pragma unroll
            for (int j = 0; j < 4; j++) s2[i][j] = 0ull;

#pragma unroll
        for (int d4 = 0; d4 < 16; d4++) {
#pragma unroll
            for (int dd = 0; dd < 4; dd++) {
                const int d = d4 * 4 + dd;
                const float* krow = &KsT[d * 128];
                ulonglong2 kA = *(const ulonglong2*)(krow + txq * 4);
                ulonglong2 kB = *(const ulonglong2*)(krow + 64 + txq * 4);
                const ULL* qcol = &Qd[(tyq * 8) * 64 + d];
#pragma unroll
                for (int i = 0; i < 8; i++) {
                    ULL qq = qcol[i * 64];          // LDS.64 broadcast
                    fma2(s2[i][0], qq, kA.x);
                    fma2(s2[i][1], qq, kA.y);
                    fma2(s2[i][2], qq, kB.x);
                    fma2(s2[i][3], qq, kB.y);
                }
            }
        }

        // ---- softmax without max-shift: p = 2^S, den += sum(p)
#pragma unroll
        for (int i = 0; i < 8; i++) {
            float p[8];
            float2 t0 = unpack2(s2[i][0]); p[0] = ex2(t0.x); p[1] = ex2(t0.y);
            float2 t1 = unpack2(s2[i][1]); p[2] = ex2(t1.x); p[3] = ex2(t1.y);
            float2 t2 = unpack2(s2[i][2]); p[4] = ex2(t2.x); p[5] = ex2(t2.y);
            float2 t3 = unpack2(s2[i][3]); p[6] = ex2(t3.x); p[7] = ex2(t3.y);
            den[i] += ((p[0] + p[1]) + (p[2] + p[3]))
                    + ((p[4] + p[5]) + (p[6] + p[7]));
            float* pr = &Ps[(tyq * 8 + i) * 128];
            *(float4*)(pr + txq * 4)      = make_float4(p[0], p[1], p[2], p[3]);
            *(float4*)(pr + 64 + txq * 4) = make_float4(p[4], p[5], p[6], p[7]);
        }

        // ---- prefetch next K/V into registers (hidden under PV)
        float4 kpre[8], vpre[8];
        const bool more = (kt + 1 < 16);
        if (more) {
            const float* Kn = Kp + (size_t)(kt + 1) * 128 * 256;
            const float* Vn = Vp + (size_t)(kt + 1) * 128 * 256;
#pragma unroll
            for (int it = 0; it < 8; it++) {
                int g = tid + it * 256;
                int s = g & 127, dg = g >> 7;
                kpre[it] = *(const float4*)(Kn + (size_t)s * 256 + dg * 4);
                int sv = g >> 4, cv = (g & 15) << 2;
                vpre[it] = *(const float4*)(Vn + (size_t)sv * 256 + cv);
            }
        }
        __syncthreads();   // A: Ps visible; all warps done with KsT

        // ---- O += P @ V : 4 rows x 8 split cols per thread (mov:fma2 1:4)
#pragma unroll
        for (int k4 = 0; k4 < 32; k4++) {
            float4 p4[4];
#pragma unroll
            for (int i = 0; i < 4; i++)
                p4[i] = *(const float4*)&Ps[(tyv * 4 + i) * 128 + k4 * 4];
#pragma unroll
            for (int kk = 0; kk < 4; kk++) {
                const float* vrow = &Vs[(k4 * 4 + kk) * 64];
                ulonglong2 vA = *(const ulonglong2*)(vrow + txv * 4);
                ulonglong2 vB = *(const ulonglong2*)(vrow + 32 + txv * 4);
#pragma unroll
                for (int i = 0; i < 4; i++) {
                    ULL pp = bcast2(((const float*)&p4[i])[kk]);
                    fma2(o2[i][0], pp, vA.x);
                    fma2(o2[i][1], pp, vA.y);
                    fma2(o2[i][2], pp, vB.x);
                    fma2(o2[i][3], pp, vB.y);
                }
            }
        }
        __syncthreads();   // B: all warps done reading Vs / Ps

        if (more) {
#pragma unroll
            for (int it = 0; it < 8; it++) {
                int g = tid + it * 256;
                int s = g & 127, dg = g >> 7;
                float4 kv = kpre[it];
                KsT[(dg * 4 + 0) * 128 + s] = kv.x;
                KsT[(dg * 4 + 1) * 128 + s] = kv.y;
                KsT[(dg * 4 + 2) * 128 + s] = kv.z;
                KsT[(dg * 4 + 3) * 128 + s] = kv.w;
                int sv = g >> 4, cv = (g & 15) << 2;
                *(float4*)&Vs[sv * 64 + cv] = vpre[it];
            }
        }
        __syncthreads();   // C: new tiles visible
    }

    // ---- denominator: reduce across 16-lane row groups, stash in smem ---
#pragma unroll
    for (int i = 0; i < 8; i++) {
#pragma unroll
        for (int off = 8; off; off >>= 1)
            den[i] += __shfl_xor_sync(0xffffffffu, den[i], off);
    }
    if (txq == 0) {
#pragma unroll
        for (int i = 0; i < 8; i++) sden[tyq * 8 + i] = den[i];
    }
    __syncthreads();

    // ---- epilogue (PV map): O / den
    float* Op = O + ((size_t)b * 2048 + q0) * 256 + h * 64;
#pragma unroll
    for (int i = 0; i < 4; i++) {
        const int row = tyv * 4 + i;
        const float inv = 1.f / sden[row];
        float2 a0 = unpack2(o2[i][0]);
        float2 a1 = unpack2(o2[i][1]);
        float2 a2 = unpack2(o2[i][2]);
        float2 a3 = unpack2(o2[i][3]);
        float* dst = Op + (size_t)row * 256;
        *(float4*)(dst + txv * 4) =
            make_float4(a0.x * inv, a0.y * inv, a1.x * inv, a1.y * inv);
        *(float4*)(dst + 32 + txv * 4) =
            make_float4(a2.x * inv, a2.y * inv, a3.x * inv, a3.y * inv);
    }
}

// ---------------- launch -------------------------------------------------
extern "C" void kernel_launch(void* const* d_in, const int* in_sizes, int n_in,
                              void* d_out, int out_size)
{
    (void)in_sizes; (void)n_in; (void)out_size;
    const float* x   = (const float*)d_in[0];
    const float* src = (const float*)d_in[1];
    const float* xpe = (const float*)d_in[2];
    const float* spe = (const float*)d_in[3];
    const float* Wq  = (const float*)d_in[4];
    const float* Wk  = (const float*)d_in[5];
    const float* Wv  = (const float*)d_in[6];
    const float* Wm  = (const float*)d_in[7];
    const float* W1  = (const float*)d_in[8];
    const float* W2  = (const float*)d_in[9];
    const float* g1  = (const float*)d_in[10];
    const float* b1  = (const float*)d_in[11];
    const float* g2  = (const float*)d_in[12];
    const float* b2  = (const float*)d_in[13];
    float* out = (float*)d_out;

    float *Qb, *Kb, *Vb, *Ob, *Msg, *Hb;
    cudaGetSymbolAddress((void**)&Qb,  g_Q);
    cudaGetSymbolAddress((void**)&Kb,  g_K);
    cudaGetSymbolAddress((void**)&Vb,  g_V);
    cudaGetSymbolAddress((void**)&Ob,  g_O);
    cudaGetSymbolAddress((void**)&Msg, g_Msg);
    cudaGetSymbolAddress((void**)&Hb,  g_H);

    // Qd 64K + Vs 32K + KsT 32K + Ps 64K + sden 0.5K
    const int ATTN_SMEM = 128 * 64 * 8 + (128 * 64 + 64 * 128 + 128 * 128 + 128) * 4;
    cudaFuncSetAttribute(attn_k, cudaFuncAttributeMaxDynamicSharedMemorySize, ATTN_SMEM);

    const dim3 blk(256);
    // fused Q/K/V projections (rotary on Q,K)
    qkv_k<<<dim3(4, 32, 3), blk>>>(x, src, xpe, spe, Wq, Wk, Wv, Qb, Kb, Vb);
    // attention
    attn_k<<<dim3(16, 8), blk, ATTN_SMEM>>>(Qb, Kb, Vb, Ob);
    // message = LN(O @ Wm)   (fused)
    gemm_ln_k<<<128, blk>>>(Ob, Wm, 256, g1, b1, nullptr, Msg);
    // h = relu(concat(x, message) @ W1)
    gemm_k<true, false><<<dim3(8, 32), blk>>>(x, Msg, 256, W1, nullptr, Hb, 4096, 512, 512);
    // out = x + LN(h @ W2)   (fused)
    gemm_ln_k<<<128, blk>>>(Hb, W2, 512, g2, b2, x, out);
}

// round 13
// speedup vs baseline: 1.2594x; 1.0367x over previous
#include <cuda_runtime.h>
#include <math.h>

typedef unsigned long long ULL;

// ---------------- f32x2 packed-math helpers (sm_100+) --------------------
__device__ __forceinline__ ULL bcast2(float v) {
    ULL r; asm("mov.b64 %0, {%1, %1};" : "=l"(r) : "f"(v)); return r;
}
__device__ __forceinline__ void fma2(ULL& d, ULL a, ULL b) {
    asm("fma.rn.f32x2 %0, %1, %2, %0;" : "+l"(d) : "l"(a), "l"(b));
}
__device__ __forceinline__ float2 unpack2(ULL v) {
    float2 f; asm("mov.b64 {%0, %1}, %2;" : "=f"(f.x), "=f"(f.y) : "l"(v)); return f;
}
__device__ __forceinline__ float ex2(float x) {
    float r; asm("ex2.approx.f32 %0, %1;" : "=f"(r) : "f"(x)); return r;
}

// ---------------- scratch buffers (no allocation allowed) ----------------
__device__ float g_Q[4096 * 256];
__device__ float g_K[4096 * 256];
__device__ float g_V[4096 * 256];
__device__ float g_O[4096 * 256];
__device__ float g_Msg[4096 * 256];
__device__ float g_H[4096 * 512];

// ---------------- GEMM core (f32x2) — R7/R10 proven version ---------------
template <bool RELU>
__device__ __forceinline__ void gemm_body(
    const float* __restrict__ A0, const float* __restrict__ A1, int kSplit,
    const float* __restrict__ W, const float* __restrict__ pe, bool rotary,
    float* __restrict__ C, int N, int K,
    float (*As)[16], float (*Ws)[64])
{
    const int tid = threadIdx.x;
    const int tx = tid & 15;
    const int ty = tid >> 4;
    const int m0 = blockIdx.y * 128;
    const int n0 = blockIdx.x * 64;

    const int ar = tid >> 2;
    const int ak = (tid & 3) * 4;
    const int wk = tid >> 4;
    const int wc = (tid & 15) * 4;

    ULL acc2[8][2];
#pragma unroll
    for (int i = 0; i < 8; i++) { acc2[i][0] = 0ull; acc2[i][1] = 0ull; }

    const int nk = K >> 4;
    float4 pa0, pa1, pw;

    pa0 = *(const float4*)(A0 + (size_t)(m0 + ar) * kSplit + ak);
    pa1 = *(const float4*)(A0 + (size_t)(m0 + ar + 64) * kSplit + ak);
    pw  = *(const float4*)(W + (size_t)wk * N + n0 + wc);
    *(float4*)&As[ar][ak]      = pa0;
    *(float4*)&As[ar + 64][ak] = pa1;
    *(float4*)&Ws[wk][wc]      = pw;
    __syncthreads();

    for (int kt = 0; kt < nk; kt++) {
        if (kt + 1 < nk) {
            const int kb = (kt + 1) << 4;
            const float* src; int lda, kk;
            if (kb < kSplit) { src = A0; lda = kSplit;     kk = kb; }
            else             { src = A1; lda = K - kSplit; kk = kb - kSplit; }
            pa0 = *(const float4*)(src + (size_t)(m0 + ar) * lda + kk + ak);
            pa1 = *(const float4*)(src + (size_t)(m0 + ar + 64) * lda + kk + ak);
            pw  = *(const float4*)(W + (size_t)(kb + wk) * N + n0 + wc);
        }
#pragma unroll
        for (int k4 = 0; k4 < 4; k4++) {
            float4 av4[8];
#pragma unroll
            for (int i = 0; i < 8; i++)
                av4[i] = *(const float4*)&As[ty * 8 + i][k4 * 4];
#pragma unroll
            for (int kk = 0; kk < 4; kk++) {
                ulonglong2 w2 = *(const ulonglong2*)&Ws[k4 * 4 + kk][tx * 4];
#pragma unroll
                for (int i = 0; i < 8; i++) {
                    ULL a2 = bcast2(((const float*)&av4[i])[kk]);
                    fma2(acc2[i][0], a2, w2.x);
                    fma2(acc2[i][1], a2, w2.y);
                }
            }
        }
        __syncthreads();
        if (kt + 1 < nk) {
            *(float4*)&As[ar][ak]      = pa0;
            *(float4*)&As[ar + 64][ak] = pa1;
            *(float4*)&Ws[wk][wc]      = pw;
        }
        __syncthreads();
    }

#pragma unroll
    for (int i = 0; i < 8; i++) {
        const int m = m0 + ty * 8 + i;
        float2 u0 = unpack2(acc2[i][0]);
        float2 u1 = unpack2(acc2[i][1]);
        float v0 = u0.x, v1 = u0.y, v2 = u1.x, v3 = u1.y;
        if (RELU) {
            v0 = fmaxf(v0, 0.f); v1 = fmaxf(v1, 0.f);
            v2 = fmaxf(v2, 0.f); v3 = fmaxf(v3, 0.f);
        }
        if (rotary) {
            const int c0 = n0 + tx * 4;
            const float* pr = pe + ((size_t)m * 256 + c0) * 2;
            float4 p0 = *(const float4*)pr;
            float4 p1 = *(const float4*)(pr + 4);
            float e = v0, o = v1;
            v0 = e * p0.x - o * p0.y;
            v1 = o * p0.z + e * p0.w;
            e = v2; o = v3;
            v2 = e * p1.x - o * p1.y;
            v3 = o * p1.z + e * p1.w;
        }
        *(float4*)(C + (size_t)m * N + n0 + tx * 4) = make_float4(v0, v1, v2, v3);
    }
}

template <bool RELU, bool ROTARY>
__global__ __launch_bounds__(256) void gemm_k(
    const float* __restrict__ A0, const float* __restrict__ A1, int kSplit,
    const float* __restrict__ W, const float* __restrict__ pe,
    float* __restrict__ C, int M, int N, int K)
{
    __shared__ __align__(16) float As[128][16];
    __shared__ __align__(16) float Ws[16][64];
    gemm_body<RELU>(A0, A1, kSplit, W, pe, ROTARY, C, N, K, As, Ws);
}

// Fused Q/K/V projection: z selects {A, W, pe, C, rotary}. 384 CTAs.
__global__ __launch_bounds__(256) void qkv_k(
    const float* __restrict__ x, const float* __restrict__ src,
    const float* __restrict__ xpe, const float* __restrict__ spe,
    const float* __restrict__ Wq, const float* __restrict__ Wk,
    const float* __restrict__ Wv,
    float* __restrict__ Qb, float* __restrict__ Kb, float* __restrict__ Vb)
{
    __shared__ __align__(16) float As[128][16];
    __shared__ __align__(16) float Ws[16][64];
    const int z = blockIdx.z;
    const float* A  = (z == 0) ? x   : src;
    const float* W  = (z == 0) ? Wq  : (z == 1 ? Wk : Wv);
    const float* pe = (z == 0) ? xpe : spe;
    float* C        = (z == 0) ? Qb  : (z == 1 ? Kb : Vb);
    gemm_body<false>(A, nullptr, 256, W, pe, z < 2, C, 256, 256, As, Ws);
}

// ---------------- GEMM + fused LayerNorm (split columns: conflict-free) ---
__global__ __launch_bounds__(256) void gemm_ln_k(
    const float* __restrict__ A, const float* __restrict__ W, int K,
    const float* __restrict__ g, const float* __restrict__ b,
    const float* __restrict__ resid, float* __restrict__ out)
{
    __shared__ __align__(16) float As[32][16];
    __shared__ __align__(16) float Ws[16][256];

    const int tid = threadIdx.x;
    const int tx = tid & 31;
    const int ty = tid >> 5;
    const int m0 = blockIdx.x * 32;

    ULL acc2[4][4];
#pragma unroll
    for (int i = 0; i < 4; i++)
#pragma unroll
        for (int j = 0; j < 4; j++) acc2[i][j] = 0ull;

    const int nk = K >> 4;
    const int ar = tid >> 2, ak = (tid & 3) * 4;

    float4 pa, pw[4];
    if (tid < 128)
        pa = *(const float4*)(A + (size_t)(m0 + ar) * K + ak);
#pragma unroll
    for (int it = 0; it < 4; it++) {
        int gidx = tid + it * 256;
        int wr = gidx >> 6, wc = (gidx & 63) * 4;
        pw[it] = *(const float4*)(W + (size_t)wr * 256 + wc);
    }
    if (tid < 128) *(float4*)&As[ar][ak] = pa;
#pragma unroll
    for (int it = 0; it < 4; it++) {
        int gidx = tid + it * 256;
        int wr = gidx >> 6, wc = (gidx & 63) * 4;
        *(float4*)&Ws[wr][wc] = pw[it];
    }
    __syncthreads();

    for (int kt = 0; kt < nk; kt++) {
        if (kt + 1 < nk) {
            const int kb = (kt + 1) << 4;
            if (tid < 128)
                pa = *(const float4*)(A + (size_t)(m0 + ar) * K + kb + ak);
#pragma unroll
            for (int it = 0; it < 4; it++) {
                int gidx = tid + it * 256;
                int wr = gidx >> 6, wc = (gidx & 63) * 4;
                pw[it] = *(const float4*)(W + (size_t)(kb + wr) * 256 + wc);
            }
        }
#pragma unroll
        for (int k4 = 0; k4 < 4; k4++) {
            float4 av4[4];
#pragma unroll
            for (int i = 0; i < 4; i++)
                av4[i] = *(const float4*)&As[ty * 4 + i][k4 * 4];
#pragma unroll
            for (int kk = 0; kk < 4; kk++) {
                const float* wrow = &Ws[k4 * 4 + kk][0];
                ulonglong2 wA = *(const ulonglong2*)(wrow + tx * 4);        // cols tx*4..+3
                ulonglong2 wB = *(const ulonglong2*)(wrow + 128 + tx * 4);  // cols 128+tx*4..+3
#pragma unroll
                for (int i = 0; i < 4; i++) {
                    ULL a2 = bcast2(((const float*)&av4[i])[kk]);
                    fma2(acc2[i][0], a2, wA.x);
                    fma2(acc2[i][1], a2, wA.y);
                    fma2(acc2[i][2], a2, wB.x);
                    fma2(acc2[i][3], a2, wB.y);
                }
            }
        }
        __syncthreads();
        if (kt + 1 < nk) {
            if (tid < 128) *(float4*)&As[ar][ak] = pa;
#pragma unroll
            for (int it = 0; it < 4; it++) {
                int gidx = tid + it * 256;
                int wr = gidx >> 6, wc = (gidx & 63) * 4;
                *(float4*)&Ws[wr][wc] = pw[it];
            }
        }
        __syncthreads();
    }

    const int c0 = tx * 4, c1 = 128 + tx * 4;
    const float4 gA = *(const float4*)(g + c0);
    const float4 gB = *(const float4*)(g + c1);
    const float4 bA = *(const float4*)(b + c0);
    const float4 bB = *(const float4*)(b + c1);

#pragma unroll
    for (int i = 0; i < 4; i++) {
        const int m = m0 + ty * 4 + i;
        float v[8];
        float2 u0 = unpack2(acc2[i][0]); v[0] = u0.x; v[1] = u0.y;
        float2 u1 = unpack2(acc2[i][1]); v[2] = u1.x; v[3] = u1.y;
        float2 u2 = unpack2(acc2[i][2]); v[4] = u2.x; v[5] = u2.y;
        float2 u3 = unpack2(acc2[i][3]); v[6] = u3.x; v[7] = u3.y;

        float s = 0.f, ss = 0.f;
#pragma unroll
        for (int j = 0; j < 8; j++) { s += v[j]; ss += v[j] * v[j]; }
#pragma unroll
        for (int off = 16; off; off >>= 1) {
            s  += __shfl_xor_sync(0xffffffffu, s, off);
            ss += __shfl_xor_sync(0xffffffffu, ss, off);
        }
        const float mu  = s * (1.f / 256.f);
        const float var = ss * (1.f / 256.f) - mu * mu;
        const float rs  = rsqrtf(var + 1e-5f);

        float r0 = (v[0] - mu) * rs * gA.x + bA.x;
        float r1 = (v[1] - mu) * rs * gA.y + bA.y;
        float r2 = (v[2] - mu) * rs * gA.z + bA.z;
        float r3 = (v[3] - mu) * rs * gA.w + bA.w;
        float r4 = (v[4] - mu) * rs * gB.x + bB.x;
        float r5 = (v[5] - mu) * rs * gB.y + bB.y;
        float r6 = (v[6] - mu) * rs * gB.z + bB.z;
        float r7 = (v[7] - mu) * rs * gB.w + bB.w;

        if (resid) {
            const float* rp = resid + (size_t)m * 256;
            float4 x0 = *(const float4*)(rp + c0);
            float4 x1 = *(const float4*)(rp + c1);
            r0 += x0.x; r1 += x0.y; r2 += x0.z; r3 += x0.w;
            r4 += x1.x; r5 += x1.y; r6 += x1.z; r7 += x1.w;
        }
        float* dst = out + (size_t)m * 256;
        *(float4*)(dst + c0) = make_float4(r0, r1, r2, r3);
        *(float4*)(dst + c1) = make_float4(r4, r5, r6, r7);
    }
}

// ---------------- FlashAttention (fp32, f32x2) — R10 + PV remap ----------
// R10 QK path verbatim (float4 q-loads + bcast2, split conflict-free K
// reads). PV remapped to 4 rows x 8 split cols per thread: movs halved
// (1024 -> 512), LDS count unchanged. Denominator handed to the PV map via
// sden. Per-element FMA order identical -> same rel_err.
__global__ __launch_bounds__(256) void attn_k(
    const float* __restrict__ Q, const float* __restrict__ Kg,
    const float* __restrict__ Vg, float* __restrict__ O)
{
    extern __shared__ __align__(16) float sm[];
    float* Qs   = sm;                     // [128][68]
    float* Vs   = Qs + 128 * 68;          // [128][68]
    float* KsT  = Vs + 128 * 68;          // [64][128]  (d, s)
    float* Ps   = KsT + 64 * 128;         // [128][128]
    float* sden = Ps + 128 * 128;         // [128]

    const int tid = threadIdx.x;
    const int tx = tid & 15;     // QK cols {tx*4, 64+tx*4}
    const int ty = tid >> 4;     // QK rows ty*8..+7
    const int txv = tid & 7;     // PV cols {txv*4, 32+txv*4}
    const int tyv = tid >> 3;    // PV rows tyv*4..+3
    const int q0 = blockIdx.x * 128;
    const int b = blockIdx.y >> 2;
    const int h = blockIdx.y & 3;

    const float* Qp = Q  + ((size_t)b * 2048 + q0) * 256 + h * 64;
    const float* Kp = Kg + (size_t)b * 2048 * 256 + h * 64;
    const float* Vp = Vg + (size_t)b * 2048 * 256 + h * 64;

    const float QSCALE = 0.18033688011112042f;  // 0.125 * log2(e)

#pragma unroll
    for (int it = 0; it < 8; it++) {
        int g = tid + it * 256;
        int r = g >> 4, c = (g & 15) << 2;
        float4 q = *(const float4*)(Qp + (size_t)r * 256 + c);
        *(float4*)&Qs[r * 68 + c] =
            make_float4(q.x * QSCALE, q.y * QSCALE, q.z * QSCALE, q.w * QSCALE);
    }
#pragma unroll
    for (int it = 0; it < 8; it++) {
        int g = tid + it * 256;
        int s = g & 127, dg = g >> 7;
        float4 kv = *(const float4*)(Kp + (size_t)s * 256 + dg * 4);
        KsT[(dg * 4 + 0) * 128 + s] = kv.x;
        KsT[(dg * 4 + 1) * 128 + s] = kv.y;
        KsT[(dg * 4 + 2) * 128 + s] = kv.z;
        KsT[(dg * 4 + 3) * 128 + s] = kv.w;
    }
#pragma unroll
    for (int it = 0; it < 8; it++) {
        int g = tid + it * 256;
        int s = g >> 4, c = (g & 15) << 2;
        *(float4*)&Vs[s * 68 + c] = *(const float4*)(Vp + (size_t)s * 256 + c);
    }
    __syncthreads();

    ULL o2[4][4];
    float den[8];
#pragma unroll
    for (int i = 0; i < 4; i++)
#pragma unroll
        for (int j = 0; j < 4; j++) o2[i][j] = 0ull;
#pragma unroll
    for (int i = 0; i < 8; i++) den[i] = 0.f;

    for (int kt = 0; kt < 16; kt++) {
        // ---- S = Q @ K^T : 8 rows x 8 split cols (R10 verbatim)
        ULL s2[8][4];
#pragma unroll
        for (int i = 0; i < 8; i++)
#pragma unroll
            for (int j = 0; j < 4; j++) s2[i][j] = 0ull;

#pragma unroll
        for (int d4 = 0; d4 < 16; d4++) {
            float4 q4[8];
#pragma unroll
            for (int i = 0; i < 8; i++)
                q4[i] = *(const float4*)&Qs[(ty * 8 + i) * 68 + d4 * 4];
#pragma unroll
            for (int dd = 0; dd < 4; dd++) {
                const float* krow = &KsT[(d4 * 4 + dd) * 128];
                ulonglong2 kA = *(const ulonglong2*)(krow + tx * 4);
                ulonglong2 kB = *(const ulonglong2*)(krow + 64 + tx * 4);
#pragma unroll
                for (int i = 0; i < 8; i++) {
                    ULL qq = bcast2(((const float*)&q4[i])[dd]);
                    fma2(s2[i][0], qq, kA.x);
                    fma2(s2[i][1], qq, kA.y);
                    fma2(s2[i][2], qq, kB.x);
                    fma2(s2[i][3], qq, kB.y);
                }
            }
        }

        // ---- softmax without max-shift: p = 2^S, den += sum(p)
#pragma unroll
        for (int i = 0; i < 8; i++) {
            float p[8];
            float2 t0 = unpack2(s2[i][0]); p[0] = ex2(t0.x); p[1] = ex2(t0.y);
            float2 t1 = unpack2(s2[i][1]); p[2] = ex2(t1.x); p[3] = ex2(t1.y);
            float2 t2 = unpack2(s2[i][2]); p[4] = ex2(t2.x); p[5] = ex2(t2.y);
            float2 t3 = unpack2(s2[i][3]); p[6] = ex2(t3.x); p[7] = ex2(t3.y);
            den[i] += ((p[0] + p[1]) + (p[2] + p[3]))
                    + ((p[4] + p[5]) + (p[6] + p[7]));
            float* pr = &Ps[(ty * 8 + i) * 128];
            *(float4*)(pr + tx * 4)      = make_float4(p[0], p[1], p[2], p[3]);
            *(float4*)(pr + 64 + tx * 4) = make_float4(p[4], p[5], p[6], p[7]);
        }

        // ---- prefetch next K/V into registers (hidden under PV)
        float4 kpre[8], vpre[8];
        const bool more = (kt + 1 < 16);
        if (more) {
            const float* Kn = Kp + (size_t)(kt + 1) * 128 * 256;
            const float* Vn = Vp + (size_t)(kt + 1) * 128 * 256;
#pragma unroll
            for (int it = 0; it < 8; it++) {
                int g = tid + it * 256;
                int s = g & 127, dg = g >> 7;
                kpre[it] = *(const float4*)(Kn + (size_t)s * 256 + dg * 4);
                int sv = g >> 4, cv = (g & 15) << 2;
                vpre[it] = *(const float4*)(Vn + (size_t)sv * 256 + cv);
            }
        }
        __syncthreads();   // A: Ps visible; all warps done with KsT

        // ---- O += P @ V : 4 rows x 8 split cols per thread (movs halved)
#pragma unroll
        for (int k4 = 0; k4 < 32; k4++) {
            float4 p4[4];
#pragma unroll
            for (int i = 0; i < 4; i++)
                p4[i] = *(const float4*)&Ps[(tyv * 4 + i) * 128 + k4 * 4];
#pragma unroll
            for (int kk = 0; kk < 4; kk++) {
                const float* vrow = &Vs[(k4 * 4 + kk) * 68];
                ulonglong2 vA = *(const ulonglong2*)(vrow + txv * 4);
                ulonglong2 vB = *(const ulonglong2*)(vrow + 32 + txv * 4);
#pragma unroll
                for (int i = 0; i < 4; i++) {
                    ULL pp = bcast2(((const float*)&p4[i])[kk]);
                    fma2(o2[i][0], pp, vA.x);
                    fma2(o2[i][1], pp, vA.y);
                    fma2(o2[i][2], pp, vB.x);
                    fma2(o2[i][3], pp, vB.y);
                }
            }
        }
        __syncthreads();   // B: all warps done reading Vs / Ps

        if (more) {
#pragma unroll
            for (int it = 0; it < 8; it++) {
                int g = tid + it * 256;
                int s = g & 127, dg = g >> 7;
                float4 kv = kpre[it];
                KsT[(dg * 4 + 0) * 128 + s] = kv.x;
                KsT[(dg * 4 + 1) * 128 + s] = kv.y;
                KsT[(dg * 4 + 2) * 128 + s] = kv.z;
                KsT[(dg * 4 + 3) * 128 + s] = kv.w;
                int sv = g >> 4, cv = (g & 15) << 2;
                *(float4*)&Vs[sv * 68 + cv] = vpre[it];
            }
        }
        __syncthreads();   // C: new tiles visible
    }

    // ---- denominator: reduce across 16-lane row groups, hand to PV map --
#pragma unroll
    for (int i = 0; i < 8; i++) {
#pragma unroll
        for (int off = 8; off; off >>= 1)
            den[i] += __shfl_xor_sync(0xffffffffu, den[i], off);
    }
    if (tx == 0) {
#pragma unroll
        for (int i = 0; i < 8; i++) sden[ty * 8 + i] = den[i];
    }
    __syncthreads();

    // ---- epilogue (PV map): O / den
    float* Op = O + ((size_t)b * 2048 + q0) * 256 + h * 64;
#pragma unroll
    for (int i = 0; i < 4; i++) {
        const int row = tyv * 4 + i;
        const float inv = 1.f / sden[row];
        float2 a0 = unpack2(o2[i][0]);
        float2 a1 = unpack2(o2[i][1]);
        float2 a2 = unpack2(o2[i][2]);
        float2 a3 = unpack2(o2[i][3]);
        float* dst = Op + (size_t)row * 256;
        *(float4*)(dst + txv * 4) =
            make_float4(a0.x * inv, a0.y * inv, a1.x * inv, a1.y * inv);
        *(float4*)(dst + 32 + txv * 4) =
            make_float4(a2.x * inv, a2.y * inv, a3.x * inv, a3.y * inv);
    }
}

// ---------------- launch -------------------------------------------------
extern "C" void kernel_launch(void* const* d_in, const int* in_sizes, int n_in,
                              void* d_out, int out_size)
{
    (void)in_sizes; (void)n_in; (void)out_size;
    const float* x   = (const float*)d_in[0];
    const float* src = (const float*)d_in[1];
    const float* xpe = (const float*)d_in[2];
    const float* spe = (const float*)d_in[3];
    const float* Wq  = (const float*)d_in[4];
    const float* Wk  = (const float*)d_in[5];
    const float* Wv  = (const float*)d_in[6];
    const float* Wm  = (const float*)d_in[7];
    const float* W1  = (const float*)d_in[8];
    const float* W2  = (const float*)d_in[9];
    const float* g1  = (const float*)d_in[10];
    const float* b1  = (const float*)d_in[11];
    const float* g2  = (const float*)d_in[12];
    const float* b2  = (const float*)d_in[13];
    float* out = (float*)d_out;

    float *Qb, *Kb, *Vb, *Ob, *Msg, *Hb;
    cudaGetSymbolAddress((void**)&Qb,  g_Q);
    cudaGetSymbolAddress((void**)&Kb,  g_K);
    cudaGetSymbolAddress((void**)&Vb,  g_V);
    cudaGetSymbolAddress((void**)&Ob,  g_O);
    cudaGetSymbolAddress((void**)&Msg, g_Msg);
    cudaGetSymbolAddress((void**)&Hb,  g_H);

    const int ATTN_SMEM = (128 * 68 + 128 * 68 + 64 * 128 + 128 * 128 + 128) * 4;
    cudaFuncSetAttribute(attn_k, cudaFuncAttributeMaxDynamicSharedMemorySize, ATTN_SMEM);

    const dim3 blk(256);
    // fused Q/K/V projections (rotary on Q,K)
    qkv_k<<<dim3(4, 32, 3), blk>>>(x, src, xpe, spe, Wq, Wk, Wv, Qb, Kb, Vb);
    // attention
    attn_k<<<dim3(16, 8), blk, ATTN_SMEM>>>(Qb, Kb, Vb, Ob);
    // message = LN(O @ Wm)   (fused)
    gemm_ln_k<<<128, blk>>>(Ob, Wm, 256, g1, b1, nullptr, Msg);
    // h = relu(concat(x, message) @ W1)
    gemm_k<true, false><<<dim3(8, 32), blk>>>(x, Msg, 256, W1, nullptr, Hb, 4096, 512, 512);
    // out = x + LN(h @ W2)   (fused)
    gemm_ln_k<<<128, blk>>>(Hb, W2, 512, g2, b2, x, out);
}